// round 10
// baseline (speedup 1.0000x reference)
#include <cuda_runtime.h>
#include <cstdint>

#define BROWS 64
#define L 16384
#define HALF 8192
#define NCTA 128
#define NT 1024
#define NW 32
#define CHUNK 8
#define NIMF 6
#define MAXIT 12
#define LPH (HALF + (HALF >> 1))
#define PH(i) ((i) + (((i) >> 3) << 2))

#define T_RUN (5 * NW + 0)
#define T_CM  (5 * NW + 1)
#define T_CNT (5 * NW + 2)
#define T_MAX (5 * NW + 3)
#define T_MIN (5 * NW + 4)

__device__ float    g_res[BROWS * L];
__device__ double   g_part[4][NCTA][4];   // depth-4 ring (speculation-safe)
__device__ unsigned g_seq[NCTA];
__device__ unsigned g_count = 0;

__device__ __forceinline__ float negInf() { return __int_as_float(0xff800000); }
__device__ __forceinline__ float posInf() { return __int_as_float(0x7f800000); }

#define CLUSTER_SYNC() do { \
    asm volatile("barrier.cluster.arrive.aligned;" ::: "memory"); \
    asm volatile("barrier.cluster.wait.aligned;" ::: "memory"); \
} while (0)

__device__ __forceinline__ void fence_cluster() {
    asm volatile("fence.acq_rel.cluster;" ::: "memory");
}
__device__ __forceinline__ void dsmem_stf(float* p, unsigned rank, float v) {
    uint32_t a = (uint32_t)__cvta_generic_to_shared(p), r;
    asm volatile("mapa.shared::cluster.u32 %0, %1, %2;" : "=r"(r) : "r"(a), "r"(rank));
    asm volatile("st.shared::cluster.f32 [%0], %1;" :: "r"(r), "f"(v) : "memory");
}
__device__ __forceinline__ void dsmem_stu(unsigned* p, unsigned rank, unsigned v) {
    uint32_t a = (uint32_t)__cvta_generic_to_shared(p), r;
    asm volatile("mapa.shared::cluster.u32 %0, %1, %2;" : "=r"(r) : "r"(a), "r"(rank));
    asm volatile("st.shared::cluster.u32 [%0], %1;" :: "r"(r), "r"(v) : "memory");
}
__device__ __forceinline__ unsigned lds_vol(const unsigned* p) {
    unsigned v;
    asm volatile("ld.volatile.shared.u32 %0, [%1];" : "=r"(v)
                 : "r"((uint32_t)__cvta_generic_to_shared(p)) : "memory");
    return v;
}
__device__ __forceinline__ void halo_push(float* rx, unsigned* rxf, unsigned peer,
                                          unsigned tag, float v) {
    dsmem_stf(&rx[tag & 3], peer, v);
    fence_cluster();
    dsmem_stu(rxf, peer, tag);
}
__device__ __forceinline__ float halo_wait(float* rx, unsigned* rxf, unsigned tag) {
    while (lds_vol(rxf) < tag) {}
    fence_cluster();
    return rx[tag & 3];
}

// fused collectives + CTA totals (totals left in ubuf[T_*])
__device__ __forceinline__ void fused_coll(unsigned vmin, unsigned vmax, unsigned vsum,
                                           float cmx, float cmn, unsigned* ubuf,
                                           unsigned& offn, unsigned& offl) {
    const int lane = threadIdx.x & 31, wid = threadIdx.x >> 5;
    unsigned imin = vmin, imax = vmax, s = vsum;
    float fx = cmx, fn = cmn;
#pragma unroll
    for (int d = 1; d < 32; d <<= 1) {
        unsigned a = __shfl_down_sync(0xffffffffu, imin, d);
        if (lane + d < 32) imin = __vminu2(imin, a);
        unsigned b = __shfl_up_sync(0xffffffffu, imax, d);
        if (lane >= d) imax = __vmaxs2(imax, b);
        s += __shfl_xor_sync(0xffffffffu, s, d);
        fx = fmaxf(fx, __shfl_xor_sync(0xffffffffu, fx, d));
        fn = fminf(fn, __shfl_xor_sync(0xffffffffu, fn, d));
    }
    if (lane == 0) {
        ubuf[wid] = imin; ubuf[2 * NW + wid] = s;
        ubuf[3 * NW + wid] = __float_as_uint(fx);
        ubuf[4 * NW + wid] = __float_as_uint(fn);
    }
    if (lane == 31) ubuf[NW + wid] = imax;
    __syncthreads();
    if (wid == 0) {
        unsigned wm = ubuf[lane], wx = ubuf[NW + lane], ws = ubuf[2 * NW + lane];
        float wfx = __uint_as_float(ubuf[3 * NW + lane]);
        float wfn = __uint_as_float(ubuf[4 * NW + lane]);
#pragma unroll
        for (int d = 1; d < 32; d <<= 1) {
            unsigned a = __shfl_down_sync(0xffffffffu, wm, d);
            if (lane + d < 32) wm = __vminu2(wm, a);
            unsigned b = __shfl_up_sync(0xffffffffu, wx, d);
            if (lane >= d) wx = __vmaxs2(wx, b);
            ws += __shfl_xor_sync(0xffffffffu, ws, d);
            wfx = fmaxf(wfx, __shfl_xor_sync(0xffffffffu, wfx, d));
            wfn = fminf(wfn, __shfl_xor_sync(0xffffffffu, wfn, d));
        }
        ubuf[lane] = wm; ubuf[NW + lane] = wx;
        if (lane == 0) {
            ubuf[T_RUN] = wm; ubuf[T_CNT] = ws;
            ubuf[T_MAX] = __float_as_uint(wfx);
            ubuf[T_MIN] = __float_as_uint(wfn);
        }
        if (lane == 31) ubuf[T_CM] = wx;
    }
    __syncthreads();
    unsigned woffn = (wid < NW - 1) ? ubuf[wid + 1] : 0x40004000u;
    unsigned lexn  = __shfl_down_sync(0xffffffffu, imin, 1);
    offn = (lane < 31) ? __vminu2(woffn, lexn) : woffn;
    unsigned woffl = (wid > 0) ? ubuf[NW + wid - 1] : 0xffffffffu;
    unsigned lexl  = __shfl_up_sync(0xffffffffu, imax, 1);
    offl = (lane > 0) ? __vmaxs2(woffl, lexl) : woffl;
}

__device__ __forceinline__ float pmax_f_excl(float v, float* wbuf) {
    const int lane = threadIdx.x & 31, wid = threadIdx.x >> 5;
    float incl = v;
#pragma unroll
    for (int d = 1; d < 32; d <<= 1) {
        float u = __shfl_up_sync(0xffffffffu, incl, d);
        if (lane >= d) incl = fmaxf(incl, u);
    }
    if (lane == 31) wbuf[wid] = incl;
    __syncthreads();
    if (wid == 0) {
        float w = wbuf[lane];
#pragma unroll
        for (int d = 1; d < 32; d <<= 1) {
            float u = __shfl_up_sync(0xffffffffu, w, d);
            if (lane >= d) w = fmaxf(w, u);
        }
        wbuf[lane] = w;
    }
    __syncthreads();
    float woff = (wid > 0) ? wbuf[wid - 1] : negInf();
    float lex  = __shfl_up_sync(0xffffffffu, incl, 1);
    float ex   = (lane > 0) ? fmaxf(woff, lex) : woff;
    __syncthreads();
    return ex;
}

__device__ __forceinline__ float pmin_f_excl(float v, float* wbuf) {
    const int lane = threadIdx.x & 31, wid = threadIdx.x >> 5;
    float incl = v;
#pragma unroll
    for (int d = 1; d < 32; d <<= 1) {
        float u = __shfl_up_sync(0xffffffffu, incl, d);
        if (lane >= d) incl = fminf(incl, u);
    }
    if (lane == 31) wbuf[wid] = incl;
    __syncthreads();
    if (wid == 0) {
        float w = wbuf[lane];
#pragma unroll
        for (int d = 1; d < 32; d <<= 1) {
            float u = __shfl_up_sync(0xffffffffu, w, d);
            if (lane >= d) w = fminf(w, u);
        }
        wbuf[lane] = w;
    }
    __syncthreads();
    float woff = (wid > 0) ? wbuf[wid - 1] : posInf();
    float lex  = __shfl_up_sync(0xffffffffu, incl, 1);
    float ex   = (lane > 0) ? fminf(woff, lex) : woff;
    __syncthreads();
    return ex;
}

__device__ __forceinline__ void block_sum2_to0(double& a, double& b, double* wbuf) {
#pragma unroll
    for (int d = 16; d; d >>= 1) {
        a += __shfl_down_sync(0xffffffffu, a, d);
        b += __shfl_down_sync(0xffffffffu, b, d);
    }
    const int lane = threadIdx.x & 31, wid = threadIdx.x >> 5;
    if (lane == 0) { wbuf[wid] = a; wbuf[NW + wid] = b; }
    __syncthreads();
    if (wid == 0) {
        double wa = wbuf[lane], wb = wbuf[NW + lane];
#pragma unroll
        for (int d = 16; d; d >>= 1) {
            wa += __shfl_down_sync(0xffffffffu, wa, d);
            wb += __shfl_down_sync(0xffffffffu, wb, d);
        }
        a = wa; b = wb;
    }
}

__device__ __forceinline__ void block_sum4_to0(double& a, double& b, double& c, double& e,
                                               double* wbuf) {
#pragma unroll
    for (int d = 16; d; d >>= 1) {
        a += __shfl_down_sync(0xffffffffu, a, d);
        b += __shfl_down_sync(0xffffffffu, b, d);
        c += __shfl_down_sync(0xffffffffu, c, d);
        e += __shfl_down_sync(0xffffffffu, e, d);
    }
    const int lane = threadIdx.x & 31, wid = threadIdx.x >> 5;
    if (lane == 0) {
        wbuf[wid] = a; wbuf[NW + wid] = b;
        wbuf[2 * NW + wid] = c; wbuf[3 * NW + wid] = e;
    }
    __syncthreads();
    if (wid == 0) {
        double wa = wbuf[lane], wb = wbuf[NW + lane];
        double wc = wbuf[2 * NW + lane], we = wbuf[3 * NW + lane];
#pragma unroll
        for (int d = 16; d; d >>= 1) {
            wa += __shfl_down_sync(0xffffffffu, wa, d);
            wb += __shfl_down_sync(0xffffffffu, wb, d);
            wc += __shfl_down_sync(0xffffffffu, wc, d);
            we += __shfl_down_sync(0xffffffffu, we, d);
        }
        a = wa; b = wb; c = wc; e = we;
    }
}

struct FS {
    unsigned mU, mL;
    int off_nu, off_nl;
    int runl_u, runl_l;
    float vl_u, vl_l;
    float fbU, fbL;
    float pFPU, pFPL;
    int few;
};

// walk A + collectives + parallel cluster exchange (values bitwise-identical to R9)
__device__ FS front(const float* __restrict__ hc, int sub,
                    unsigned* ubuf, float* fbuf,
                    float* rxh, unsigned* rxh_f,
                    float (*rxm)[9], unsigned* rxm_f,
                    unsigned hp, unsigned mp)
{
    const int t = threadIdx.x;
    const int lo = t * CHUNK;
    const int loG = sub * HALF;
    const int gbase = loG + lo;
    const unsigned peer = (unsigned)(sub ^ 1);

    float h8[CHUNK];
    const float* cbase = hc + PH(lo);
    *(float4*)&h8[0] = ((const float4*)cbase)[0];
    *(float4*)&h8[4] = ((const float4*)cbase)[1];

    float prev, nextB;
    if (t > 0)           prev = hc[PH(lo - 1)];
    else if (sub == 1)   prev = halo_wait(rxh, rxh_f, hp);
    else                 prev = 0.f;
    if (t < NT - 1)      nextB = hc[PH(lo + CHUNK)];
    else if (sub == 0)   nextB = halo_wait(rxh, rxh_f, hp);
    else                 nextB = 0.f;

    unsigned mU = 0, mL = 0;
    float cmx = negInf(), cmn = posInf();
#pragma unroll
    for (int j = 0; j < CHUNK; ++j) {
        float cur = h8[j];
        float nxt = (j < CHUNK - 1) ? h8[j + 1] : nextB;
        mU |= (unsigned)((prev < cur) & (cur > nxt)) << j;
        mL |= (unsigned)((prev > cur) & (cur < nxt)) << j;
        cmx = fmaxf(cmx, cur); cmn = fminf(cmn, cur);
        prev = cur;
    }
    if (sub == 0 && t == 0)      { mU &= ~1u;   mL &= ~1u;   }
    if (sub == 1 && t == NT - 1) { mU &= 0x7fu; mL &= 0x7fu; }

    int run_u = mU ? gbase + (__ffs(mU) - 1) : L;
    int run_l = mL ? gbase + (__ffs(mL) - 1) : L;
    int cm_u  = mU ? gbase + (31 - __clz((int)mU)) : -1;
    int cm_l  = mL ? gbase + (31 - __clz((int)mL)) : -1;
    unsigned cnt = (unsigned)__popc(mU) | ((unsigned)__popc(mL) << 16);

    unsigned offn, offl;
    fused_coll((unsigned)run_u | ((unsigned)run_l << 16),
               ((unsigned)cm_u & 0xffffu) | (((unsigned)cm_l & 0xffffu) << 16),
               cnt, cmx, cmn, ubuf, offn, offl);

    // lanes 0-8 push mailbox words in parallel; t0 releases tag
    if (t < 9) {
        unsigned tr = ubuf[T_RUN], tc = ubuf[T_CM];
        float val;
        if      (t == 0) val = __uint_as_float(tr);
        else if (t == 1) val = __uint_as_float(tc);
        else if (t == 2) val = __uint_as_float(ubuf[T_CNT]);
        else if (t == 3) val = __uint_as_float(ubuf[T_MAX]);
        else if (t == 4) val = __uint_as_float(ubuf[T_MIN]);
        else if (t == 5) { int fu  = (int)(tr & 0xffffu);        val = (fu  < L)  ? hc[PH(fu  - loG)] : 0.f; }
        else if (t == 6) { int fl2 = (int)(tr >> 16);            val = (fl2 < L)  ? hc[PH(fl2 - loG)] : 0.f; }
        else if (t == 7) { int lu  = (int)(short)(tc & 0xffffu); val = (lu  >= 0) ? hc[PH(lu  - loG)] : 0.f; }
        else             { int ll  = (int)(short)(tc >> 16);     val = (ll  >= 0) ? hc[PH(ll  - loG)] : 0.f; }
        dsmem_stf(&rxm[mp & 3][t], peer, val);
        fence_cluster();
    }
    __syncwarp();
    if (t == 0) { fence_cluster(); dsmem_stu(rxm_f, peer, mp); }
    // all threads wait for peer's mailbox locally
    while (lds_vol(rxm_f) < mp) {}
    fence_cluster();
    const float* pv = rxm[mp & 3];
    float p0 = pv[0], p1 = pv[1], p2 = pv[2], p3 = pv[3], p4 = pv[4];
    float pFPU = pv[5], pFPL = pv[6], pLPU = pv[7], pLPL = pv[8];

    unsigned totc = ubuf[T_CNT] + __float_as_uint(p2);
    if (sub == 0) offn = __vminu2(offn, __float_as_uint(p0));
    else          offl = __vmaxs2(offl, __float_as_uint(p1));

    FS st;
    st.mU = mU; st.mL = mL;
    st.off_nu = (int)(offn & 0xffffu);
    st.off_nl = (int)(offn >> 16);
    st.runl_u = (int)(short)(offl & 0xffffu);
    st.runl_l = (int)(short)(offl >> 16);
    bool few_u = (totc & 0xffffu) < 2u;
    bool few_l = (totc >> 16)     < 2u;
    st.few = (few_u ? 1 : 0) | (few_l ? 2 : 0);
    st.fbU = negInf(); st.fbL = posInf();
    if (few_u) {
        float ex = pmax_f_excl(cmx, fbuf);
        st.fbU = (sub == 1) ? fmaxf(ex, p3) : ex;
    }
    if (few_l) {
        float ex = pmin_f_excl(cmn, fbuf);
        st.fbL = (sub == 1) ? fminf(ex, p4) : ex;
    }
    st.vl_u = (st.runl_u >= loG) ? hc[PH(st.runl_u - loG)] : pLPU;
    st.vl_l = (st.runl_l >= loG) ? hc[PH(st.runl_l - loG)] : pLPL;
    st.pFPU = pFPU; st.pFPL = pFPL;
    return st;
}

// walk B (R9-identical arithmetic) + halo push of ho edges
__device__ void walkB(const float* __restrict__ hc, float* __restrict__ ho,
                      FS st, int sub,
                      float* rxh, unsigned* rxh_f, unsigned hp_out,
                      float& o_m, float& o_h2)
{
    const int t = threadIdx.x;
    const int lo = t * CHUNK;
    const int loG = sub * HALF, hiG = loG + HALF;
    const int gbase = loG + lo;
    const unsigned peer = (unsigned)(sub ^ 1);

    float h8[CHUNK];
    const float* cbase = hc + PH(lo);
    *(float4*)&h8[0] = ((const float4*)cbase)[0];
    *(float4*)&h8[4] = ((const float4*)cbase)[1];

    const bool few_u = (st.few & 1) != 0, few_l = (st.few & 2) != 0;
    int   runl_u = st.runl_u, runl_l = st.runl_l;
    float vl_u = st.vl_u, vl_l = st.vl_l;
    float fbU = st.fbU, fbL = st.fbL;
    int   cur_nu = -0x40000000, cur_nl = -0x40000000;
    float vr_u = 0.f, vr_l = 0.f;
    float acc_m = 0.f, acc_h = 0.f;
    float firstO = 0.f, lastO = 0.f;
    float* obase = ho + PH(lo);

#pragma unroll
    for (int q = 0; q < 2; ++q) {
        float4 ov;
#pragma unroll
        for (int r = 0; r < 4; ++r) {
            const int j = 4 * q + r;
            const int gi = gbase + j;
            const float hv = h8[j];

            if ((st.mU >> j) & 1u) { runl_u = gi; vl_u = hv; }
            unsigned remU = st.mU >> j;
            int nu = remU ? gi + (__ffs(remU) - 1) : st.off_nu;
            if (nu != cur_nu) { cur_nu = nu; vr_u = (nu < hiG) ? hc[PH(nu - loG)] : st.pFPU; }
            float eu;
            {
                int den = nu - runl_u;
                eu = (den > 0) ? vl_u + ((float)(gi - runl_u) / (float)den) * (vr_u - vl_u)
                               : vl_u;
                if (runl_u < 0) eu = vr_u;
                if (nu >= L)    eu = vl_u;
            }
            if (few_u) { fbU = fmaxf(fbU, hv); eu = fbU; }

            if ((st.mL >> j) & 1u) { runl_l = gi; vl_l = hv; }
            unsigned remL = st.mL >> j;
            int nl = remL ? gi + (__ffs(remL) - 1) : st.off_nl;
            if (nl != cur_nl) { cur_nl = nl; vr_l = (nl < hiG) ? hc[PH(nl - loG)] : st.pFPL; }
            float el;
            {
                int den = nl - runl_l;
                el = (den > 0) ? vl_l + ((float)(gi - runl_l) / (float)den) * (vr_l - vl_l)
                               : vl_l;
                if (runl_l < 0) el = vr_l;
                if (nl >= L)    el = vl_l;
            }
            if (few_l) { fbL = fminf(fbL, hv); el = fbL; }

            float mean = 0.5f * (eu + el);
            float o = hv - mean;
            if (j == 0) firstO = o;
            lastO = o;
            acc_m += mean * mean;
            acc_h += hv * hv;
            switch (r) {
                case 0: ov.x = o; break;
                case 1: ov.y = o; break;
                case 2: ov.z = o; break;
                default: ov.w = o; break;
            }
        }
        ((float4*)obase)[q] = ov;
    }
    o_m = acc_m; o_h2 = acc_h;

    if (sub == 0 && t == NT - 1) halo_push(rxh, rxh_f, peer, hp_out, lastO);
    if (sub == 1 && t == 0)      halo_push(rxh, rxh_f, peer, hp_out, firstO);
}

// grid-wide sd decision for an already-published tag
__device__ __forceinline__ int resolve2(unsigned tagv, double* s_d2, int* s_flag) {
    const int t = threadIdx.x;
    if (t < NCTA) {
        volatile unsigned* sq = &g_seq[t];
        while (*sq < tagv) {}
    }
    __threadfence();
    if (t < NCTA) {
        volatile double* p = &g_part[tagv & 3][t][0];
        double a = p[0], b = p[1];
#pragma unroll
        for (int d = 16; d; d >>= 1) {
            a += __shfl_down_sync(0xffffffffu, a, d);
            b += __shfl_down_sync(0xffffffffu, b, d);
        }
        if ((t & 31) == 0) { s_d2[t >> 5] = a; s_d2[4 + (t >> 5)] = b; }
    }
    __syncthreads();
    if (t == 0) {
        double A  = (s_d2[0] + s_d2[1]) + (s_d2[2] + s_d2[3]);
        double Bs = (s_d2[4] + s_d2[5]) + (s_d2[6] + s_d2[7]);
        *s_flag = (A / (Bs + 1e-8) < 0.05) ? 1 : 0;
    }
    __syncthreads();
    return *s_flag;
}

__global__ void __launch_bounds__(NT, 1) __cluster_dims__(2, 1, 1)
emd_kernel(const float* __restrict__ x, float* __restrict__ out)
{
    extern __shared__ unsigned char dynsm[];
    float* B0 = (float*)dynsm;
    float* B1 = B0 + LPH;
    float* B2 = B1 + LPH;
    float* Bf[3] = {B0, B1, B2};

    __shared__ unsigned s_u[5 * NW + 5];
    __shared__ float    s_f[NW + 1];
    __shared__ double   s_d[4 * NW];
    __shared__ double   s_d2[16];
    __shared__ int      s_flag;
    __shared__ float    s_rxh[4];
    __shared__ float    s_rxm[4][9];
    __shared__ unsigned s_rxh_f, s_rxm_f;

    const int t   = threadIdx.x;
    const int lo  = t * CHUNK;
    const int cta = blockIdx.x;
    const int row = cta >> 1;
    unsigned rk;
    asm("mov.u32 %0, %%cluster_ctarank;" : "=r"(rk));
    const int sub = (int)rk;
    const unsigned peer = (unsigned)(sub ^ 1);

    if (t == 0) { s_rxh_f = 0u; s_rxm_f = 0u; }
    __syncthreads();
    CLUSTER_SYNC();

    const float* xr   = x + (size_t)row * L + sub * HALF;
    float*       resr = g_res + (size_t)row * L + sub * HALF;
#pragma unroll
    for (int q = 0; q < 2; ++q)
        *(float4*)(resr + lo + 4 * q) = *(const float4*)(xr + lo + 4 * q);

    unsigned tag = 1, hp = 0, mp = 0;
    bool outer_done = false;

    for (int im = 0; im < NIMF; ++im) {
        float* outim = out + ((size_t)im * BROWS + row) * L + sub * HALF;
        if (outer_done) {
            float4 z = make_float4(0.f, 0.f, 0.f, 0.f);
#pragma unroll
            for (int q = 0; q < 2; ++q) *(float4*)(outim + lo + 4 * q) = z;
            continue;  // globally uniform
        }

        // load residual into buffer 0
#pragma unroll
        for (int q = 0; q < 2; ++q)
            ((float4*)(Bf[0] + PH(lo)))[q] = *(const float4*)(resr + lo + 4 * q);
        __syncthreads();

        hp++;
        if (sub == 0 && t == NT - 1) halo_push(s_rxh, &s_rxh_f, peer, hp, Bf[0][PH(HALF - 1)]);
        if (sub == 1 && t == 0)      halo_push(s_rxh, &s_rxh_f, peer, hp, Bf[0][PH(0)]);
        mp++;
        FS st = front(Bf[0], sub, s_u, s_f, s_rxh, &s_rxh_f, s_rxm, &s_rxm_f, hp, mp);

        // 3-buffer rotation: cur = h_it, prv = h_{it-1} (kept for rollback), tgt = free
        int cur = 0, tgt = 1, oth = 2, prv = -1;
        int finalb = -1;

        for (int it = 0; it < MAXIT; ++it) {
            float fm, fh2;
            hp++;
            walkB(Bf[cur], Bf[tgt], st, sub, s_rxh, &s_rxh_f, hp, fm, fh2);
            double sm = (double)fm, sh2 = (double)fh2;
            block_sum2_to0(sm, sh2, s_d);
            if (t == 0) {
                double* p = &g_part[tag & 3][cta][0];
                p[0] = sm; p[1] = sh2;
                __threadfence();
                ((volatile unsigned*)g_seq)[cta] = tag;
            }
            tag++;
            if (it + 1 < MAXIT) {
                mp++;
                st = front(Bf[tgt], sub, s_u, s_f, s_rxh, &s_rxh_f, s_rxm, &s_rxm_f, hp, mp);
            }
            if (it > 0) {
                if (resolve2(tag - 2, s_d2, &s_flag)) { finalb = prv; break; }
            }
            int nf = (it == 0) ? oth : prv;
            prv = cur; cur = tgt; tgt = nf;
        }
        if (finalb < 0)
            finalb = resolve2(tag - 1, s_d2, &s_flag) ? prv : cur;

        float* hfin = Bf[finalb];
        float* sc   = Bf[(finalb + 1) % 3];

        // emit IMF, update residual
        float ar = 0.f, ar2 = 0.f;
#pragma unroll
        for (int q = 0; q < 2; ++q) {
            float4 hv = ((const float4*)(hfin + PH(lo)))[q];
            float4 rr = *(const float4*)(resr + lo + 4 * q);
            float4 nr;
            nr.x = rr.x - hv.x; nr.y = rr.y - hv.y;
            nr.z = rr.z - hv.z; nr.w = rr.w - hv.w;
            *(float4*)(outim + lo + 4 * q) = hv;
            *(float4*)(resr + lo + 4 * q)  = nr;
            ((float4*)(sc + PH(lo)))[q]    = nr;
            ar  += nr.x + nr.y + nr.z + nr.w;
            ar2 += nr.x * nr.x + nr.y * nr.y + nr.z * nr.z + nr.w * nr.w;
        }
        __syncthreads();
        hp++;
        if (sub == 0 && t == NT - 1) halo_push(s_rxh, &s_rxh_f, peer, hp, sc[PH(HALF - 1)]);
        if (sub == 1 && t == 0)      halo_push(s_rxh, &s_rxh_f, peer, hp, sc[PH(0)]);

        float ad = 0.f, ad2 = 0.f;
        {
            float c8[CHUNK];
#pragma unroll
            for (int q = 0; q < 2; ++q)
                *(float4*)&c8[4 * q] = ((const float4*)(sc + PH(lo)))[q];
            float nb;
            if (t < NT - 1)    nb = sc[PH(lo + CHUNK)];
            else if (sub == 0) nb = halo_wait(s_rxh, &s_rxh_f, hp);
            else               nb = 0.f;
#pragma unroll
            for (int j = 0; j < CHUNK; ++j) {
                float nx = (j < CHUNK - 1) ? c8[j + 1] : nb;
                if (sub * HALF + lo + j < L - 1) {
                    float d = nx - c8[j];
                    ad  += d;
                    ad2 += d * d;
                }
            }
        }
        double Sd = (double)ad, Sd2 = (double)ad2;
        double Sr = (double)ar, Sr2 = (double)ar2;
        block_sum4_to0(Sd, Sd2, Sr, Sr2, s_d);
        if (t == 0) {
            double* p = &g_part[tag & 3][cta][0];
            p[0] = Sd; p[1] = Sd2; p[2] = Sr; p[3] = Sr2;
            __threadfence();
            ((volatile unsigned*)g_seq)[cta] = tag;
        }
        if (t < NCTA) {
            volatile unsigned* sq = &g_seq[t];
            while (*sq < tag) {}
        }
        __threadfence();
        if (t < NCTA) {
            volatile double* p = &g_part[tag & 3][t][0];
            double a = p[0], b = p[1], c = p[2], e = p[3];
#pragma unroll
            for (int d = 16; d; d >>= 1) {
                a += __shfl_down_sync(0xffffffffu, a, d);
                b += __shfl_down_sync(0xffffffffu, b, d);
                c += __shfl_down_sync(0xffffffffu, c, d);
                e += __shfl_down_sync(0xffffffffu, e, d);
            }
            if ((t & 31) == 0) {
                int w = t >> 5;
                s_d2[4 * w + 0] = a; s_d2[4 * w + 1] = b;
                s_d2[4 * w + 2] = c; s_d2[4 * w + 3] = e;
            }
        }
        __syncthreads();
        if (t == 0) {
            double a = (s_d2[0] + s_d2[4]) + (s_d2[8] + s_d2[12]);
            double b = (s_d2[1] + s_d2[5]) + (s_d2[9] + s_d2[13]);
            double c = (s_d2[2] + s_d2[6]) + (s_d2[10] + s_d2[14]);
            double e = (s_d2[3] + s_d2[7]) + (s_d2[11] + s_d2[15]);
            double ndv = (double)BROWS * (double)(L - 1);
            double nrv = (double)BROWS * (double)L;
            double vard = (b - a * a / ndv) / (ndv - 1.0);
            double varr = (e - c * c / nrv) / (nrv - 1.0);
            s_flag = (vard < 0.05 * varr) ? 1 : 0;
        }
        tag++;
        __syncthreads();
        if (s_flag) outer_done = true;
    }

    float* outres = out + ((size_t)NIMF * BROWS + row) * L + sub * HALF;
#pragma unroll
    for (int q = 0; q < 2; ++q)
        *(float4*)(outres + lo + 4 * q) = *(const float4*)(resr + lo + 4 * q);

    // end-of-launch rendezvous + reset for graph replays
    __syncthreads();
    if (t == 0) {
        __threadfence();
        atomicAdd(&g_count, 1u);
    }
    if (cta == 0) {
        if (t == 0) {
            volatile unsigned* vc = &g_count;
            while (*vc < (unsigned)NCTA) {}
            __threadfence();
        }
        __syncthreads();
        if (t < NCTA) ((volatile unsigned*)g_seq)[t] = 0u;
        if (t == 0) g_count = 0u;
    }
    CLUSTER_SYNC();
}

extern "C" void kernel_launch(void* const* d_in, const int* in_sizes, int n_in,
                              void* d_out, int out_size) {
    (void)in_sizes; (void)n_in; (void)out_size;
    const size_t shmem = (size_t)(3 * LPH) * sizeof(float);
    cudaFuncSetAttribute(emd_kernel, cudaFuncAttributeMaxDynamicSharedMemorySize, (int)shmem);
    emd_kernel<<<NCTA, NT, shmem>>>((const float*)d_in[0], (float*)d_out);
}

// round 11
// speedup vs baseline: 1.1482x; 1.1482x over previous
#include <cuda_runtime.h>
#include <cstdint>

#define BROWS 64
#define L 16384
#define HALF 8192
#define NCTA 128
#define NT 1024
#define NW 32
#define CHUNK 8
#define NIMF 6
#define MAXIT 12
#define LPH (HALF + (HALF >> 1))
#define PH(i) ((i) + (((i) >> 3) << 2))

#define T_RUN (3 * NW + 0)
#define T_CM  (3 * NW + 1)
#define T_CNT (3 * NW + 2)

__device__ float    g_res[BROWS * L];
__device__ double   g_part[2][NCTA][4];
__device__ unsigned g_seq[NCTA];
__device__ unsigned g_count = 0;

__device__ __forceinline__ float negInf() { return __int_as_float(0xff800000); }
__device__ __forceinline__ float posInf() { return __int_as_float(0x7f800000); }

#define CLUSTER_SYNC() do { \
    asm volatile("barrier.cluster.arrive.aligned;" ::: "memory"); \
    asm volatile("barrier.cluster.wait.aligned;" ::: "memory"); \
} while (0)

__device__ __forceinline__ void fence_cluster() {
    asm volatile("fence.acq_rel.cluster;" ::: "memory");
}
__device__ __forceinline__ void dsmem_stf(float* p, unsigned rank, float v) {
    uint32_t a = (uint32_t)__cvta_generic_to_shared(p), r;
    asm volatile("mapa.shared::cluster.u32 %0, %1, %2;" : "=r"(r) : "r"(a), "r"(rank));
    asm volatile("st.shared::cluster.f32 [%0], %1;" :: "r"(r), "f"(v) : "memory");
}
__device__ __forceinline__ void dsmem_stu(unsigned* p, unsigned rank, unsigned v) {
    uint32_t a = (uint32_t)__cvta_generic_to_shared(p), r;
    asm volatile("mapa.shared::cluster.u32 %0, %1, %2;" : "=r"(r) : "r"(a), "r"(rank));
    asm volatile("st.shared::cluster.u32 [%0], %1;" :: "r"(r), "r"(v) : "memory");
}
__device__ __forceinline__ unsigned lds_vol(const unsigned* p) {
    unsigned v;
    asm volatile("ld.volatile.shared.u32 %0, [%1];" : "=r"(v)
                 : "r"((uint32_t)__cvta_generic_to_shared(p)) : "memory");
    return v;
}
__device__ __forceinline__ void halo_push(float* rx, unsigned* rxf, unsigned peer,
                                          unsigned tag, float v) {
    dsmem_stf(&rx[tag & 3], peer, v);
    fence_cluster();
    dsmem_stu(rxf, peer, tag);
}
__device__ __forceinline__ float halo_wait(float* rx, unsigned* rxf, unsigned tag) {
    while (lds_vol(rxf) < tag) {}
    fence_cluster();
    return rx[tag & 3];
}

// fused collectives: packed suffix-min / prefix-max / sum; CTA totals in ubuf[T_*]
__device__ __forceinline__ void fused_coll(unsigned vmin, unsigned vmax, unsigned vsum,
                                           unsigned* ubuf,
                                           unsigned& offn, unsigned& offl) {
    const int lane = threadIdx.x & 31, wid = threadIdx.x >> 5;
    unsigned imin = vmin, imax = vmax, s = vsum;
#pragma unroll
    for (int d = 1; d < 32; d <<= 1) {
        unsigned a = __shfl_down_sync(0xffffffffu, imin, d);
        if (lane + d < 32) imin = __vminu2(imin, a);
        unsigned b = __shfl_up_sync(0xffffffffu, imax, d);
        if (lane >= d) imax = __vmaxs2(imax, b);
        s += __shfl_xor_sync(0xffffffffu, s, d);
    }
    if (lane == 0)  { ubuf[wid] = imin; ubuf[2 * NW + wid] = s; }
    if (lane == 31) ubuf[NW + wid] = imax;
    __syncthreads();
    if (wid == 0) {
        unsigned wm = ubuf[lane], wx = ubuf[NW + lane], ws = ubuf[2 * NW + lane];
#pragma unroll
        for (int d = 1; d < 32; d <<= 1) {
            unsigned a = __shfl_down_sync(0xffffffffu, wm, d);
            if (lane + d < 32) wm = __vminu2(wm, a);
            unsigned b = __shfl_up_sync(0xffffffffu, wx, d);
            if (lane >= d) wx = __vmaxs2(wx, b);
            ws += __shfl_xor_sync(0xffffffffu, ws, d);
        }
        ubuf[lane] = wm; ubuf[NW + lane] = wx;
        if (lane == 0)  { ubuf[T_RUN] = wm; ubuf[T_CNT] = ws; }
        if (lane == 31) ubuf[T_CM] = wx;
    }
    __syncthreads();
    unsigned woffn = (wid < NW - 1) ? ubuf[wid + 1] : 0x40004000u;
    unsigned lexn  = __shfl_down_sync(0xffffffffu, imin, 1);
    offn = (lane < 31) ? __vminu2(woffn, lexn) : woffn;
    unsigned woffl = (wid > 0) ? ubuf[NW + wid - 1] : 0xffffffffu;
    unsigned lexl  = __shfl_up_sync(0xffffffffu, imax, 1);
    offl = (lane > 0) ? __vmaxs2(woffl, lexl) : woffl;
}

__device__ __forceinline__ float pmax_f_excl(float v, float* wbuf) {
    const int lane = threadIdx.x & 31, wid = threadIdx.x >> 5;
    float incl = v;
#pragma unroll
    for (int d = 1; d < 32; d <<= 1) {
        float u = __shfl_up_sync(0xffffffffu, incl, d);
        if (lane >= d) incl = fmaxf(incl, u);
    }
    if (lane == 31) wbuf[wid] = incl;
    __syncthreads();
    if (wid == 0) {
        float w = wbuf[lane];
#pragma unroll
        for (int d = 1; d < 32; d <<= 1) {
            float u = __shfl_up_sync(0xffffffffu, w, d);
            if (lane >= d) w = fmaxf(w, u);
        }
        wbuf[lane] = w;
    }
    __syncthreads();
    float woff = (wid > 0) ? wbuf[wid - 1] : negInf();
    float lex  = __shfl_up_sync(0xffffffffu, incl, 1);
    float ex   = (lane > 0) ? fmaxf(woff, lex) : woff;
    __syncthreads();
    return ex;
}

__device__ __forceinline__ float pmin_f_excl(float v, float* wbuf) {
    const int lane = threadIdx.x & 31, wid = threadIdx.x >> 5;
    float incl = v;
#pragma unroll
    for (int d = 1; d < 32; d <<= 1) {
        float u = __shfl_up_sync(0xffffffffu, incl, d);
        if (lane >= d) incl = fminf(incl, u);
    }
    if (lane == 31) wbuf[wid] = incl;
    __syncthreads();
    if (wid == 0) {
        float w = wbuf[lane];
#pragma unroll
        for (int d = 1; d < 32; d <<= 1) {
            float u = __shfl_up_sync(0xffffffffu, w, d);
            if (lane >= d) w = fminf(w, u);
        }
        wbuf[lane] = w;
    }
    __syncthreads();
    float woff = (wid > 0) ? wbuf[wid - 1] : posInf();
    float lex  = __shfl_up_sync(0xffffffffu, incl, 1);
    float ex   = (lane > 0) ? fminf(woff, lex) : woff;
    __syncthreads();
    return ex;
}

__device__ __forceinline__ float block_max_tot(float v, float* wbuf) {
#pragma unroll
    for (int d = 16; d; d >>= 1) v = fmaxf(v, __shfl_xor_sync(0xffffffffu, v, d));
    const int lane = threadIdx.x & 31, wid = threadIdx.x >> 5;
    if (lane == 0) wbuf[wid] = v;
    __syncthreads();
    if (wid == 0) {
        float w = wbuf[lane];
#pragma unroll
        for (int d = 16; d; d >>= 1) w = fmaxf(w, __shfl_xor_sync(0xffffffffu, w, d));
        if (lane == 0) wbuf[0] = w;
    }
    __syncthreads();
    float r = wbuf[0];
    __syncthreads();
    return r;
}

__device__ __forceinline__ float block_min_tot(float v, float* wbuf) {
#pragma unroll
    for (int d = 16; d; d >>= 1) v = fminf(v, __shfl_xor_sync(0xffffffffu, v, d));
    const int lane = threadIdx.x & 31, wid = threadIdx.x >> 5;
    if (lane == 0) wbuf[wid] = v;
    __syncthreads();
    if (wid == 0) {
        float w = wbuf[lane];
#pragma unroll
        for (int d = 16; d; d >>= 1) w = fminf(w, __shfl_xor_sync(0xffffffffu, w, d));
        if (lane == 0) wbuf[0] = w;
    }
    __syncthreads();
    float r = wbuf[0];
    __syncthreads();
    return r;
}

__device__ __forceinline__ void block_sum2_to0(double& a, double& b, double* wbuf) {
#pragma unroll
    for (int d = 16; d; d >>= 1) {
        a += __shfl_down_sync(0xffffffffu, a, d);
        b += __shfl_down_sync(0xffffffffu, b, d);
    }
    const int lane = threadIdx.x & 31, wid = threadIdx.x >> 5;
    if (lane == 0) { wbuf[wid] = a; wbuf[NW + wid] = b; }
    __syncthreads();
    if (wid == 0) {
        double wa = wbuf[lane], wb = wbuf[NW + lane];
#pragma unroll
        for (int d = 16; d; d >>= 1) {
            wa += __shfl_down_sync(0xffffffffu, wa, d);
            wb += __shfl_down_sync(0xffffffffu, wb, d);
        }
        a = wa; b = wb;
    }
}

__device__ __forceinline__ void block_sum4_to0(double& a, double& b, double& c, double& e,
                                               double* wbuf) {
#pragma unroll
    for (int d = 16; d; d >>= 1) {
        a += __shfl_down_sync(0xffffffffu, a, d);
        b += __shfl_down_sync(0xffffffffu, b, d);
        c += __shfl_down_sync(0xffffffffu, c, d);
        e += __shfl_down_sync(0xffffffffu, e, d);
    }
    const int lane = threadIdx.x & 31, wid = threadIdx.x >> 5;
    if (lane == 0) {
        wbuf[wid] = a; wbuf[NW + wid] = b;
        wbuf[2 * NW + wid] = c; wbuf[3 * NW + wid] = e;
    }
    __syncthreads();
    if (wid == 0) {
        double wa = wbuf[lane], wb = wbuf[NW + lane];
        double wc = wbuf[2 * NW + lane], we = wbuf[3 * NW + lane];
#pragma unroll
        for (int d = 16; d; d >>= 1) {
            wa += __shfl_down_sync(0xffffffffu, wa, d);
            wb += __shfl_down_sync(0xffffffffu, wb, d);
            wc += __shfl_down_sync(0xffffffffu, wc, d);
            we += __shfl_down_sync(0xffffffffu, we, d);
        }
        a = wa; b = wb; c = wc; e = we;
    }
}

struct FS {
    unsigned mU, mL;
    int off_nu, off_nl;
    int runl_u, runl_l;
    float vl_u, vl_l;
    float fbU, fbL;
    float pFPU, pFPL;
    int few;
};

// walk A + collectives + parallel cluster exchange (values bitwise-identical to R9)
__device__ FS front(const float* __restrict__ hc, int sub,
                    unsigned* ubuf, float* fbuf,
                    float* rxh, unsigned* rxh_f,
                    float (*rxm)[9], unsigned* rxm_f,
                    unsigned hp, unsigned& mp)
{
    const int t = threadIdx.x;
    const int lo = t * CHUNK;
    const int loG = sub * HALF;
    const int gbase = loG + lo;
    const unsigned peer = (unsigned)(sub ^ 1);
    mp++;

    float h8[CHUNK];
    const float* cbase = hc + PH(lo);
    *(float4*)&h8[0] = ((const float4*)cbase)[0];
    *(float4*)&h8[4] = ((const float4*)cbase)[1];

    float prev, nextB;
    if (t > 0)           prev = hc[PH(lo - 1)];
    else if (sub == 1)   prev = halo_wait(rxh, rxh_f, hp);
    else                 prev = 0.f;
    if (t < NT - 1)      nextB = hc[PH(lo + CHUNK)];
    else if (sub == 0)   nextB = halo_wait(rxh, rxh_f, hp);
    else                 nextB = 0.f;

    unsigned mU = 0, mL = 0;
#pragma unroll
    for (int j = 0; j < CHUNK; ++j) {
        float cur = h8[j];
        float nxt = (j < CHUNK - 1) ? h8[j + 1] : nextB;
        mU |= (unsigned)((prev < cur) & (cur > nxt)) << j;
        mL |= (unsigned)((prev > cur) & (cur < nxt)) << j;
        prev = cur;
    }
    if (sub == 0 && t == 0)      { mU &= ~1u;   mL &= ~1u;   }
    if (sub == 1 && t == NT - 1) { mU &= 0x7fu; mL &= 0x7fu; }

    int run_u = mU ? gbase + (__ffs(mU) - 1) : L;
    int run_l = mL ? gbase + (__ffs(mL) - 1) : L;
    int cm_u  = mU ? gbase + (31 - __clz((int)mU)) : -1;
    int cm_l  = mL ? gbase + (31 - __clz((int)mL)) : -1;
    unsigned cnt = (unsigned)__popc(mU) | ((unsigned)__popc(mL) << 16);

    unsigned offn, offl;
    fused_coll((unsigned)run_u | ((unsigned)run_l << 16),
               ((unsigned)cm_u & 0xffffu) | (((unsigned)cm_l & 0xffffu) << 16),
               cnt, ubuf, offn, offl);

    // lanes 0-6 push mailbox words in parallel; t0 releases tag
    if (t < 7) {
        unsigned tr = ubuf[T_RUN], tc = ubuf[T_CM];
        float val;
        if      (t == 0) val = __uint_as_float(tr);
        else if (t == 1) val = __uint_as_float(tc);
        else if (t == 2) val = __uint_as_float(ubuf[T_CNT]);
        else if (t == 3) { int fu  = (int)(tr & 0xffffu);        val = (fu  < L)  ? hc[PH(fu  - loG)] : 0.f; }
        else if (t == 4) { int fl2 = (int)(tr >> 16);            val = (fl2 < L)  ? hc[PH(fl2 - loG)] : 0.f; }
        else if (t == 5) { int lu  = (int)(short)(tc & 0xffffu); val = (lu  >= 0) ? hc[PH(lu  - loG)] : 0.f; }
        else             { int ll  = (int)(short)(tc >> 16);     val = (ll  >= 0) ? hc[PH(ll  - loG)] : 0.f; }
        dsmem_stf(&rxm[mp & 3][t], peer, val);
        fence_cluster();
    }
    __syncwarp();
    if (t == 0) { fence_cluster(); dsmem_stu(rxm_f, peer, mp); }
    while (lds_vol(rxm_f) < mp) {}
    fence_cluster();
    const float* pv = rxm[mp & 3];
    float p0 = pv[0], p1 = pv[1], p2 = pv[2];
    float pFPU = pv[3], pFPL = pv[4], pLPU = pv[5], pLPL = pv[6];

    unsigned totc = ubuf[T_CNT] + __float_as_uint(p2);
    if (sub == 0) offn = __vminu2(offn, __float_as_uint(p0));
    else          offl = __vmaxs2(offl, __float_as_uint(p1));

    FS st;
    st.mU = mU; st.mL = mL;
    st.off_nu = (int)(offn & 0xffffu);
    st.off_nl = (int)(offn >> 16);
    st.runl_u = (int)(short)(offl & 0xffffu);
    st.runl_l = (int)(short)(offl >> 16);
    bool few_u = (totc & 0xffffu) < 2u;
    bool few_l = (totc >> 16)     < 2u;
    st.few = (few_u ? 1 : 0) | (few_l ? 2 : 0);
    st.fbU = negInf(); st.fbL = posInf();
    if (few_u | few_l) {
        // rare fallback path: recompute chunk extremes, extra 2-word exchange
        float cmx = negInf(), cmn = posInf();
#pragma unroll
        for (int j = 0; j < CHUNK; ++j) { cmx = fmaxf(cmx, h8[j]); cmn = fminf(cmn, h8[j]); }
        float totU = block_max_tot(cmx, fbuf);
        float totL = block_min_tot(cmn, fbuf);
        mp++;   // cluster-uniform (few derived from exchanged totals)
        if (t == 0) dsmem_stf(&rxm[mp & 3][0], peer, totU);
        if (t == 1) dsmem_stf(&rxm[mp & 3][1], peer, totL);
        if (t < 2) fence_cluster();
        __syncwarp();
        if (t == 0) { fence_cluster(); dsmem_stu(rxm_f, peer, mp); }
        while (lds_vol(rxm_f) < mp) {}
        fence_cluster();
        float peerU = rxm[mp & 3][0], peerL = rxm[mp & 3][1];
        if (few_u) {
            float ex = pmax_f_excl(cmx, fbuf);
            st.fbU = (sub == 1) ? fmaxf(ex, peerU) : ex;
        }
        if (few_l) {
            float ex = pmin_f_excl(cmn, fbuf);
            st.fbL = (sub == 1) ? fminf(ex, peerL) : ex;
        }
    }
    st.vl_u = (st.runl_u >= loG) ? hc[PH(st.runl_u - loG)] : pLPU;
    st.vl_l = (st.runl_l >= loG) ? hc[PH(st.runl_l - loG)] : pLPL;
    st.pFPU = pFPU; st.pFPL = pFPL;
    return st;
}

// walk B: bitwise-identical envelope values, fewer instructions
__device__ void walkB(const float* __restrict__ hc, float* __restrict__ ho,
                      FS st, int sub,
                      float* rxh, unsigned* rxh_f, unsigned hp_out,
                      float& o_m, float& o_h2)
{
    const int t = threadIdx.x;
    const int lo = t * CHUNK;
    const int loG = sub * HALF, hiG = loG + HALF;
    const int gbase = loG + lo;
    const unsigned peer = (unsigned)(sub ^ 1);

    float h8[CHUNK];
    const float* cbase = hc + PH(lo);
    *(float4*)&h8[0] = ((const float4*)cbase)[0];
    *(float4*)&h8[4] = ((const float4*)cbase)[1];

    const bool few_u = (st.few & 1) != 0, few_l = (st.few & 2) != 0;
    const bool mayL_u = (st.runl_u < 0),  mayL_l = (st.runl_l < 0);
    const bool mayR_u = (st.off_nu >= L), mayR_l = (st.off_nl >= L);
    int   runl_u = st.runl_u, runl_l = st.runl_l;
    float vl_u = st.vl_u, vl_l = st.vl_l;
    float fbU = st.fbU, fbL = st.fbL;
    int   cur_nu = -0x40000000, cur_nl = -0x40000000;
    float vr_u = 0.f, vr_l = 0.f;
    float fden_u = 1.f, fden_l = 1.f;
    float du_u = (float)(gbase - st.runl_u);   // exact: |.| < 2^24
    float du_l = (float)(gbase - st.runl_l);
    float acc_m = 0.f, acc_h = 0.f;
    float firstO = 0.f, lastO = 0.f;
    float* obase = ho + PH(lo);

#pragma unroll
    for (int q = 0; q < 2; ++q) {
        float4 ov;
#pragma unroll
        for (int r = 0; r < 4; ++r) {
            const int j = 4 * q + r;
            const int gi = gbase + j;
            const float hv = h8[j];

            const bool pkU = (st.mU >> j) & 1u;
            if (pkU) { runl_u = gi; vl_u = hv; du_u = 0.f; }
            unsigned remU = st.mU >> j;
            int nu = remU ? gi + (__ffs(remU) - 1) : st.off_nu;
            if (nu != cur_nu) {
                cur_nu = nu;
                vr_u = (nu < hiG) ? hc[PH(nu - loG)] : st.pFPU;
                fden_u = (float)(nu - runl_u);   // exact int->float
            }
            // den == 0  <=>  peak at gi (runl <= gi <= nu, equality only at peaks)
            float eu = pkU ? vl_u : vl_u + (du_u / fden_u) * (vr_u - vl_u);
            if (mayL_u && runl_u < 0) eu = vr_u;   // left of first peak
            if (mayR_u && nu >= L)    eu = vl_u;   // right of last peak
            if (few_u) { fbU = fmaxf(fbU, hv); eu = fbU; }
            du_u += 1.0f;

            const bool pkL = (st.mL >> j) & 1u;
            if (pkL) { runl_l = gi; vl_l = hv; du_l = 0.f; }
            unsigned remL = st.mL >> j;
            int nl = remL ? gi + (__ffs(remL) - 1) : st.off_nl;
            if (nl != cur_nl) {
                cur_nl = nl;
                vr_l = (nl < hiG) ? hc[PH(nl - loG)] : st.pFPL;
                fden_l = (float)(nl - runl_l);
            }
            float el = pkL ? vl_l : vl_l + (du_l / fden_l) * (vr_l - vl_l);
            if (mayL_l && runl_l < 0) el = vr_l;
            if (mayR_l && nl >= L)    el = vl_l;
            if (few_l) { fbL = fminf(fbL, hv); el = fbL; }
            du_l += 1.0f;

            float mean = 0.5f * (eu + el);
            float o = hv - mean;
            if (j == 0) firstO = o;
            lastO = o;
            acc_m += mean * mean;
            acc_h += hv * hv;
            switch (r) {
                case 0: ov.x = o; break;
                case 1: ov.y = o; break;
                case 2: ov.z = o; break;
                default: ov.w = o; break;
            }
        }
        ((float4*)obase)[q] = ov;
    }
    o_m = acc_m; o_h2 = acc_h;

    if (sub == 0 && t == NT - 1) halo_push(rxh, rxh_f, peer, hp_out, lastO);
    if (sub == 1 && t == 0)      halo_push(rxh, rxh_f, peer, hp_out, firstO);
}

__global__ void __launch_bounds__(NT, 1) __cluster_dims__(2, 1, 1)
emd_kernel(const float* __restrict__ x, float* __restrict__ out)
{
    extern __shared__ unsigned char dynsm[];
    float* bufA = (float*)dynsm;
    float* bufB = bufA + LPH;

    __shared__ unsigned s_u[3 * NW + 3];
    __shared__ float    s_f[NW + 1];
    __shared__ double   s_d[4 * NW];
    __shared__ double   s_d2[16];
    __shared__ int      s_flag;
    __shared__ float    s_rxh[4];
    __shared__ float    s_rxm[4][9];
    __shared__ unsigned s_rxh_f, s_rxm_f;

    const int t   = threadIdx.x;
    const int lo  = t * CHUNK;
    const int cta = blockIdx.x;
    const int row = cta >> 1;
    unsigned rk;
    asm("mov.u32 %0, %%cluster_ctarank;" : "=r"(rk));
    const int sub = (int)rk;
    const unsigned peer = (unsigned)(sub ^ 1);

    if (t == 0) { s_rxh_f = 0u; s_rxm_f = 0u; }
    __syncthreads();
    CLUSTER_SYNC();   // flags initialized in both CTAs before any remote push

    const float* xr   = x + (size_t)row * L + sub * HALF;
    float*       resr = g_res + (size_t)row * L + sub * HALF;
#pragma unroll
    for (int q = 0; q < 2; ++q)
        *(float4*)(resr + lo + 4 * q) = *(const float4*)(xr + lo + 4 * q);

    unsigned tag = 1, hp = 0, mp = 0;
    bool outer_done = false;

    for (int im = 0; im < NIMF; ++im) {
        float* outim = out + ((size_t)im * BROWS + row) * L + sub * HALF;
        if (outer_done) {
            float4 z = make_float4(0.f, 0.f, 0.f, 0.f);
#pragma unroll
            for (int q = 0; q < 2; ++q) *(float4*)(outim + lo + 4 * q) = z;
            continue;  // globally uniform
        }

        float* hc = bufA;
        float* ho = bufB;
#pragma unroll
        for (int q = 0; q < 2; ++q)
            ((float4*)(hc + PH(lo)))[q] = *(const float4*)(resr + lo + 4 * q);
        __syncthreads();

        hp++;
        if (sub == 0 && t == NT - 1) halo_push(s_rxh, &s_rxh_f, peer, hp, hc[PH(HALF - 1)]);
        if (sub == 1 && t == 0)      halo_push(s_rxh, &s_rxh_f, peer, hp, hc[PH(0)]);
        FS st = front(hc, sub, s_u, s_f, s_rxh, &s_rxh_f, s_rxm, &s_rxm_f, hp, mp);

        for (int it = 0; it < MAXIT; ++it) {
            float fm, fh2;
            hp++;
            walkB(hc, ho, st, sub, s_rxh, &s_rxh_f, hp, fm, fh2);
            double sm = (double)fm, sh2 = (double)fh2;
            block_sum2_to0(sm, sh2, s_d);
            if (t == 0) {
                double* p = &g_part[tag & 1][cta][0];
                p[0] = sm; p[1] = sh2;
                __threadfence();
                ((volatile unsigned*)g_seq)[cta] = tag;
            }
            // speculative front for next iteration, hidden under the grid sync
            FS st2;
            const bool spec = (it + 1 < MAXIT);
            if (spec)
                st2 = front(ho, sub, s_u, s_f, s_rxh, &s_rxh_f, s_rxm, &s_rxm_f, hp, mp);
            if (t < NCTA) {
                volatile unsigned* sq = &g_seq[t];
                while (*sq < tag) {}
            }
            __threadfence();
            if (t < NCTA) {
                volatile double* p = &g_part[tag & 1][t][0];
                double a = p[0], b = p[1];
#pragma unroll
                for (int d = 16; d; d >>= 1) {
                    a += __shfl_down_sync(0xffffffffu, a, d);
                    b += __shfl_down_sync(0xffffffffu, b, d);
                }
                if ((t & 31) == 0) { s_d2[t >> 5] = a; s_d2[4 + (t >> 5)] = b; }
            }
            __syncthreads();
            if (t == 0) {
                double A  = (s_d2[0] + s_d2[1]) + (s_d2[2] + s_d2[3]);
                double Bs = (s_d2[4] + s_d2[5]) + (s_d2[6] + s_d2[7]);
                s_flag = (A / (Bs + 1e-8) < 0.05) ? 1 : 0;
            }
            tag++;
            __syncthreads();
            if (s_flag) break;
            float* tmp = hc; hc = ho; ho = tmp;
            st = st2;
        }

        // emit IMF, update residual
        float ar = 0.f, ar2 = 0.f;
#pragma unroll
        for (int q = 0; q < 2; ++q) {
            float4 hv = ((const float4*)(hc + PH(lo)))[q];
            float4 rr = *(const float4*)(resr + lo + 4 * q);
            float4 nr;
            nr.x = rr.x - hv.x; nr.y = rr.y - hv.y;
            nr.z = rr.z - hv.z; nr.w = rr.w - hv.w;
            *(float4*)(outim + lo + 4 * q) = hv;
            *(float4*)(resr + lo + 4 * q)  = nr;
            ((float4*)(ho + PH(lo)))[q]    = nr;
            ar  += nr.x + nr.y + nr.z + nr.w;
            ar2 += nr.x * nr.x + nr.y * nr.y + nr.z * nr.z + nr.w * nr.w;
        }
        __syncthreads();
        hp++;
        if (sub == 0 && t == NT - 1) halo_push(s_rxh, &s_rxh_f, peer, hp, ho[PH(HALF - 1)]);
        if (sub == 1 && t == 0)      halo_push(s_rxh, &s_rxh_f, peer, hp, ho[PH(0)]);

        float ad = 0.f, ad2 = 0.f;
        {
            float c8[CHUNK];
#pragma unroll
            for (int q = 0; q < 2; ++q)
                *(float4*)&c8[4 * q] = ((const float4*)(ho + PH(lo)))[q];
            float nb;
            if (t < NT - 1)    nb = ho[PH(lo + CHUNK)];
            else if (sub == 0) nb = halo_wait(s_rxh, &s_rxh_f, hp);
            else               nb = 0.f;
#pragma unroll
            for (int j = 0; j < CHUNK; ++j) {
                float nx = (j < CHUNK - 1) ? c8[j + 1] : nb;
                if (sub * HALF + lo + j < L - 1) {
                    float d = nx - c8[j];
                    ad  += d;
                    ad2 += d * d;
                }
            }
        }
        double Sd = (double)ad, Sd2 = (double)ad2;
        double Sr = (double)ar, Sr2 = (double)ar2;
        block_sum4_to0(Sd, Sd2, Sr, Sr2, s_d);
        if (t == 0) {
            double* p = &g_part[tag & 1][cta][0];
            p[0] = Sd; p[1] = Sd2; p[2] = Sr; p[3] = Sr2;
            __threadfence();
            ((volatile unsigned*)g_seq)[cta] = tag;
        }
        if (t < NCTA) {
            volatile unsigned* sq = &g_seq[t];
            while (*sq < tag) {}
        }
        __threadfence();
        if (t < NCTA) {
            volatile double* p = &g_part[tag & 1][t][0];
            double a = p[0], b = p[1], c = p[2], e = p[3];
#pragma unroll
            for (int d = 16; d; d >>= 1) {
                a += __shfl_down_sync(0xffffffffu, a, d);
                b += __shfl_down_sync(0xffffffffu, b, d);
                c += __shfl_down_sync(0xffffffffu, c, d);
                e += __shfl_down_sync(0xffffffffu, e, d);
            }
            if ((t & 31) == 0) {
                int w = t >> 5;
                s_d2[4 * w + 0] = a; s_d2[4 * w + 1] = b;
                s_d2[4 * w + 2] = c; s_d2[4 * w + 3] = e;
            }
        }
        __syncthreads();
        if (t == 0) {
            double a = (s_d2[0] + s_d2[4]) + (s_d2[8] + s_d2[12]);
            double b = (s_d2[1] + s_d2[5]) + (s_d2[9] + s_d2[13]);
            double c = (s_d2[2] + s_d2[6]) + (s_d2[10] + s_d2[14]);
            double e = (s_d2[3] + s_d2[7]) + (s_d2[11] + s_d2[15]);
            double ndv = (double)BROWS * (double)(L - 1);
            double nrv = (double)BROWS * (double)L;
            double vard = (b - a * a / ndv) / (ndv - 1.0);
            double varr = (e - c * c / nrv) / (nrv - 1.0);
            s_flag = (vard < 0.05 * varr) ? 1 : 0;
        }
        tag++;
        __syncthreads();
        if (s_flag) outer_done = true;
    }

    float* outres = out + ((size_t)NIMF * BROWS + row) * L + sub * HALF;
#pragma unroll
    for (int q = 0; q < 2; ++q)
        *(float4*)(outres + lo + 4 * q) = *(const float4*)(resr + lo + 4 * q);

    // end-of-launch rendezvous + reset for graph replays
    __syncthreads();
    if (t == 0) {
        __threadfence();
        atomicAdd(&g_count, 1u);
    }
    if (cta == 0) {
        if (t == 0) {
            volatile unsigned* vc = &g_count;
            while (*vc < (unsigned)NCTA) {}
            __threadfence();
        }
        __syncthreads();
        if (t < NCTA) ((volatile unsigned*)g_seq)[t] = 0u;
        if (t == 0) g_count = 0u;
    }
    CLUSTER_SYNC();   // no CTA exits while peer may still remote-write its smem
}

extern "C" void kernel_launch(void* const* d_in, const int* in_sizes, int n_in,
                              void* d_out, int out_size) {
    (void)in_sizes; (void)n_in; (void)out_size;
    const size_t shmem = (size_t)(2 * LPH) * sizeof(float);
    cudaFuncSetAttribute(emd_kernel, cudaFuncAttributeMaxDynamicSharedMemorySize, (int)shmem);
    emd_kernel<<<NCTA, NT, shmem>>>((const float*)d_in[0], (float*)d_out);
}

// round 12
// speedup vs baseline: 1.2217x; 1.0640x over previous
#include <cuda_runtime.h>
#include <cstdint>

#define BROWS 64
#define L 16384
#define HALF 8192
#define NCTA 128
#define NT 1024
#define NW 32
#define CHUNK 8
#define NIMF 6
#define MAXIT 12
#define LPH (HALF + (HALF >> 1))
#define PH(i) ((i) + (((i) >> 3) << 2))

#define T_RUN (3 * NW + 0)
#define T_CM  (3 * NW + 1)
#define T_CNT (3 * NW + 2)

__device__ float    g_res[BROWS * L];
__device__ double   g_part[2][NCTA][4];
__device__ unsigned g_seq[NCTA];
__device__ unsigned g_count = 0;

__device__ __forceinline__ float negInf() { return __int_as_float(0xff800000); }
__device__ __forceinline__ float posInf() { return __int_as_float(0x7f800000); }

#define CLUSTER_SYNC() do { \
    asm volatile("barrier.cluster.arrive.aligned;" ::: "memory"); \
    asm volatile("barrier.cluster.wait.aligned;" ::: "memory"); \
} while (0)

__device__ __forceinline__ void fence_cluster() {
    asm volatile("fence.acq_rel.cluster;" ::: "memory");
}
__device__ __forceinline__ void dsmem_stf(float* p, unsigned rank, float v) {
    uint32_t a = (uint32_t)__cvta_generic_to_shared(p), r;
    asm volatile("mapa.shared::cluster.u32 %0, %1, %2;" : "=r"(r) : "r"(a), "r"(rank));
    asm volatile("st.shared::cluster.f32 [%0], %1;" :: "r"(r), "f"(v) : "memory");
}
__device__ __forceinline__ void dsmem_stu(unsigned* p, unsigned rank, unsigned v) {
    uint32_t a = (uint32_t)__cvta_generic_to_shared(p), r;
    asm volatile("mapa.shared::cluster.u32 %0, %1, %2;" : "=r"(r) : "r"(a), "r"(rank));
    asm volatile("st.shared::cluster.u32 [%0], %1;" :: "r"(r), "r"(v) : "memory");
}
__device__ __forceinline__ unsigned lds_vol(const unsigned* p) {
    unsigned v;
    asm volatile("ld.volatile.shared.u32 %0, [%1];" : "=r"(v)
                 : "r"((uint32_t)__cvta_generic_to_shared(p)) : "memory");
    return v;
}
__device__ __forceinline__ void halo_push(float* rx, unsigned* rxf, unsigned peer,
                                          unsigned tag, float v) {
    dsmem_stf(&rx[tag & 3], peer, v);
    fence_cluster();
    dsmem_stu(rxf, peer, tag);
}
__device__ __forceinline__ float halo_wait(float* rx, unsigned* rxf, unsigned tag) {
    while (lds_vol(rxf) < tag) {}
    fence_cluster();
    return rx[tag & 3];
}

// fused collectives: packed suffix-min / prefix-max / sum; CTA totals in ubuf[T_*]
__device__ __forceinline__ void fused_coll(unsigned vmin, unsigned vmax, unsigned vsum,
                                           unsigned* ubuf,
                                           unsigned& offn, unsigned& offl) {
    const int lane = threadIdx.x & 31, wid = threadIdx.x >> 5;
    unsigned imin = vmin, imax = vmax, s = vsum;
#pragma unroll
    for (int d = 1; d < 32; d <<= 1) {
        unsigned a = __shfl_down_sync(0xffffffffu, imin, d);
        if (lane + d < 32) imin = __vminu2(imin, a);
        unsigned b = __shfl_up_sync(0xffffffffu, imax, d);
        if (lane >= d) imax = __vmaxs2(imax, b);
        s += __shfl_xor_sync(0xffffffffu, s, d);
    }
    if (lane == 0)  { ubuf[wid] = imin; ubuf[2 * NW + wid] = s; }
    if (lane == 31) ubuf[NW + wid] = imax;
    __syncthreads();
    if (wid == 0) {
        unsigned wm = ubuf[lane], wx = ubuf[NW + lane], ws = ubuf[2 * NW + lane];
#pragma unroll
        for (int d = 1; d < 32; d <<= 1) {
            unsigned a = __shfl_down_sync(0xffffffffu, wm, d);
            if (lane + d < 32) wm = __vminu2(wm, a);
            unsigned b = __shfl_up_sync(0xffffffffu, wx, d);
            if (lane >= d) wx = __vmaxs2(wx, b);
            ws += __shfl_xor_sync(0xffffffffu, ws, d);
        }
        ubuf[lane] = wm; ubuf[NW + lane] = wx;
        if (lane == 0)  { ubuf[T_RUN] = wm; ubuf[T_CNT] = ws; }
        if (lane == 31) ubuf[T_CM] = wx;
    }
    __syncthreads();
    unsigned woffn = (wid < NW - 1) ? ubuf[wid + 1] : 0x40004000u;
    unsigned lexn  = __shfl_down_sync(0xffffffffu, imin, 1);
    offn = (lane < 31) ? __vminu2(woffn, lexn) : woffn;
    unsigned woffl = (wid > 0) ? ubuf[NW + wid - 1] : 0xffffffffu;
    unsigned lexl  = __shfl_up_sync(0xffffffffu, imax, 1);
    offl = (lane > 0) ? __vmaxs2(woffl, lexl) : woffl;
}

__device__ __forceinline__ float pmax_f_excl(float v, float* wbuf) {
    const int lane = threadIdx.x & 31, wid = threadIdx.x >> 5;
    float incl = v;
#pragma unroll
    for (int d = 1; d < 32; d <<= 1) {
        float u = __shfl_up_sync(0xffffffffu, incl, d);
        if (lane >= d) incl = fmaxf(incl, u);
    }
    if (lane == 31) wbuf[wid] = incl;
    __syncthreads();
    if (wid == 0) {
        float w = wbuf[lane];
#pragma unroll
        for (int d = 1; d < 32; d <<= 1) {
            float u = __shfl_up_sync(0xffffffffu, w, d);
            if (lane >= d) w = fmaxf(w, u);
        }
        wbuf[lane] = w;
    }
    __syncthreads();
    float woff = (wid > 0) ? wbuf[wid - 1] : negInf();
    float lex  = __shfl_up_sync(0xffffffffu, incl, 1);
    float ex   = (lane > 0) ? fmaxf(woff, lex) : woff;
    __syncthreads();
    return ex;
}

__device__ __forceinline__ float pmin_f_excl(float v, float* wbuf) {
    const int lane = threadIdx.x & 31, wid = threadIdx.x >> 5;
    float incl = v;
#pragma unroll
    for (int d = 1; d < 32; d <<= 1) {
        float u = __shfl_up_sync(0xffffffffu, incl, d);
        if (lane >= d) incl = fminf(incl, u);
    }
    if (lane == 31) wbuf[wid] = incl;
    __syncthreads();
    if (wid == 0) {
        float w = wbuf[lane];
#pragma unroll
        for (int d = 1; d < 32; d <<= 1) {
            float u = __shfl_up_sync(0xffffffffu, w, d);
            if (lane >= d) w = fminf(w, u);
        }
        wbuf[lane] = w;
    }
    __syncthreads();
    float woff = (wid > 0) ? wbuf[wid - 1] : posInf();
    float lex  = __shfl_up_sync(0xffffffffu, incl, 1);
    float ex   = (lane > 0) ? fminf(woff, lex) : woff;
    __syncthreads();
    return ex;
}

__device__ __forceinline__ float block_max_tot(float v, float* wbuf) {
#pragma unroll
    for (int d = 16; d; d >>= 1) v = fmaxf(v, __shfl_xor_sync(0xffffffffu, v, d));
    const int lane = threadIdx.x & 31, wid = threadIdx.x >> 5;
    if (lane == 0) wbuf[wid] = v;
    __syncthreads();
    if (wid == 0) {
        float w = wbuf[lane];
#pragma unroll
        for (int d = 16; d; d >>= 1) w = fmaxf(w, __shfl_xor_sync(0xffffffffu, w, d));
        if (lane == 0) wbuf[0] = w;
    }
    __syncthreads();
    float r = wbuf[0];
    __syncthreads();
    return r;
}

__device__ __forceinline__ float block_min_tot(float v, float* wbuf) {
#pragma unroll
    for (int d = 16; d; d >>= 1) v = fminf(v, __shfl_xor_sync(0xffffffffu, v, d));
    const int lane = threadIdx.x & 31, wid = threadIdx.x >> 5;
    if (lane == 0) wbuf[wid] = v;
    __syncthreads();
    if (wid == 0) {
        float w = wbuf[lane];
#pragma unroll
        for (int d = 16; d; d >>= 1) w = fminf(w, __shfl_xor_sync(0xffffffffu, w, d));
        if (lane == 0) wbuf[0] = w;
    }
    __syncthreads();
    float r = wbuf[0];
    __syncthreads();
    return r;
}

__device__ __forceinline__ void block_sum2_to0(double& a, double& b, double* wbuf) {
#pragma unroll
    for (int d = 16; d; d >>= 1) {
        a += __shfl_down_sync(0xffffffffu, a, d);
        b += __shfl_down_sync(0xffffffffu, b, d);
    }
    const int lane = threadIdx.x & 31, wid = threadIdx.x >> 5;
    if (lane == 0) { wbuf[wid] = a; wbuf[NW + wid] = b; }
    __syncthreads();
    if (wid == 0) {
        double wa = wbuf[lane], wb = wbuf[NW + lane];
#pragma unroll
        for (int d = 16; d; d >>= 1) {
            wa += __shfl_down_sync(0xffffffffu, wa, d);
            wb += __shfl_down_sync(0xffffffffu, wb, d);
        }
        a = wa; b = wb;
    }
}

__device__ __forceinline__ void block_sum4_to0(double& a, double& b, double& c, double& e,
                                               double* wbuf) {
#pragma unroll
    for (int d = 16; d; d >>= 1) {
        a += __shfl_down_sync(0xffffffffu, a, d);
        b += __shfl_down_sync(0xffffffffu, b, d);
        c += __shfl_down_sync(0xffffffffu, c, d);
        e += __shfl_down_sync(0xffffffffu, e, d);
    }
    const int lane = threadIdx.x & 31, wid = threadIdx.x >> 5;
    if (lane == 0) {
        wbuf[wid] = a; wbuf[NW + wid] = b;
        wbuf[2 * NW + wid] = c; wbuf[3 * NW + wid] = e;
    }
    __syncthreads();
    if (wid == 0) {
        double wa = wbuf[lane], wb = wbuf[NW + lane];
        double wc = wbuf[2 * NW + lane], we = wbuf[3 * NW + lane];
#pragma unroll
        for (int d = 16; d; d >>= 1) {
            wa += __shfl_down_sync(0xffffffffu, wa, d);
            wb += __shfl_down_sync(0xffffffffu, wb, d);
            wc += __shfl_down_sync(0xffffffffu, wc, d);
            we += __shfl_down_sync(0xffffffffu, we, d);
        }
        a = wa; b = wb; c = wc; e = we;
    }
}

struct FS {
    unsigned mU, mL;
    int off_nu, off_nl;
    int runl_u, runl_l;
    float vl_u, vl_l;
    float fbU, fbL;
    float pFPU, pFPL;
    int few;
};

// walk A + collectives + parallel cluster exchange
__device__ FS front(const float* __restrict__ hc, int sub,
                    unsigned* ubuf, float* fbuf,
                    float* rxh, unsigned* rxh_f,
                    float (*rxm)[9], unsigned* rxm_f,
                    unsigned hp, unsigned& mp)
{
    const int t = threadIdx.x;
    const int lo = t * CHUNK;
    const int loG = sub * HALF;
    const int gbase = loG + lo;
    const unsigned peer = (unsigned)(sub ^ 1);
    mp++;

    float h8[CHUNK];
    const float* cbase = hc + PH(lo);
    *(float4*)&h8[0] = ((const float4*)cbase)[0];
    *(float4*)&h8[4] = ((const float4*)cbase)[1];

    float prev, nextB;
    if (t > 0)           prev = hc[PH(lo - 1)];
    else if (sub == 1)   prev = halo_wait(rxh, rxh_f, hp);
    else                 prev = 0.f;
    if (t < NT - 1)      nextB = hc[PH(lo + CHUNK)];
    else if (sub == 0)   nextB = halo_wait(rxh, rxh_f, hp);
    else                 nextB = 0.f;

    unsigned mU = 0, mL = 0;
#pragma unroll
    for (int j = 0; j < CHUNK; ++j) {
        float cur = h8[j];
        float nxt = (j < CHUNK - 1) ? h8[j + 1] : nextB;
        mU |= (unsigned)((prev < cur) & (cur > nxt)) << j;
        mL |= (unsigned)((prev > cur) & (cur < nxt)) << j;
        prev = cur;
    }
    if (sub == 0 && t == 0)      { mU &= ~1u;   mL &= ~1u;   }
    if (sub == 1 && t == NT - 1) { mU &= 0x7fu; mL &= 0x7fu; }

    int run_u = mU ? gbase + (__ffs(mU) - 1) : L;
    int run_l = mL ? gbase + (__ffs(mL) - 1) : L;
    int cm_u  = mU ? gbase + (31 - __clz((int)mU)) : -1;
    int cm_l  = mL ? gbase + (31 - __clz((int)mL)) : -1;
    unsigned cnt = (unsigned)__popc(mU) | ((unsigned)__popc(mL) << 16);

    unsigned offn, offl;
    fused_coll((unsigned)run_u | ((unsigned)run_l << 16),
               ((unsigned)cm_u & 0xffffu) | (((unsigned)cm_l & 0xffffu) << 16),
               cnt, ubuf, offn, offl);

    // lanes 0-6 push mailbox words in parallel; t0 releases tag
    if (t < 7) {
        unsigned tr = ubuf[T_RUN], tc = ubuf[T_CM];
        float val;
        if      (t == 0) val = __uint_as_float(tr);
        else if (t == 1) val = __uint_as_float(tc);
        else if (t == 2) val = __uint_as_float(ubuf[T_CNT]);
        else if (t == 3) { int fu  = (int)(tr & 0xffffu);        val = (fu  < L)  ? hc[PH(fu  - loG)] : 0.f; }
        else if (t == 4) { int fl2 = (int)(tr >> 16);            val = (fl2 < L)  ? hc[PH(fl2 - loG)] : 0.f; }
        else if (t == 5) { int lu  = (int)(short)(tc & 0xffffu); val = (lu  >= 0) ? hc[PH(lu  - loG)] : 0.f; }
        else             { int ll  = (int)(short)(tc >> 16);     val = (ll  >= 0) ? hc[PH(ll  - loG)] : 0.f; }
        dsmem_stf(&rxm[mp & 3][t], peer, val);
        fence_cluster();
    }
    __syncwarp();
    if (t == 0) { fence_cluster(); dsmem_stu(rxm_f, peer, mp); }
    while (lds_vol(rxm_f) < mp) {}
    fence_cluster();
    const float* pv = rxm[mp & 3];
    float p0 = pv[0], p1 = pv[1], p2 = pv[2];
    float pFPU = pv[3], pFPL = pv[4], pLPU = pv[5], pLPL = pv[6];

    unsigned totc = ubuf[T_CNT] + __float_as_uint(p2);
    if (sub == 0) offn = __vminu2(offn, __float_as_uint(p0));
    else          offl = __vmaxs2(offl, __float_as_uint(p1));

    FS st;
    st.mU = mU; st.mL = mL;
    st.off_nu = (int)(offn & 0xffffu);
    st.off_nl = (int)(offn >> 16);
    st.runl_u = (int)(short)(offl & 0xffffu);
    st.runl_l = (int)(short)(offl >> 16);
    bool few_u = (totc & 0xffffu) < 2u;
    bool few_l = (totc >> 16)     < 2u;
    st.few = (few_u ? 1 : 0) | (few_l ? 2 : 0);
    st.fbU = negInf(); st.fbL = posInf();
    if (few_u | few_l) {
        // rare fallback path: recompute chunk extremes, extra 2-word exchange
        float cmx = negInf(), cmn = posInf();
#pragma unroll
        for (int j = 0; j < CHUNK; ++j) { cmx = fmaxf(cmx, h8[j]); cmn = fminf(cmn, h8[j]); }
        float totU = block_max_tot(cmx, fbuf);
        float totL = block_min_tot(cmn, fbuf);
        mp++;   // cluster-uniform (few derived from exchanged totals)
        if (t == 0) dsmem_stf(&rxm[mp & 3][0], peer, totU);
        if (t == 1) dsmem_stf(&rxm[mp & 3][1], peer, totL);
        if (t < 2) fence_cluster();
        __syncwarp();
        if (t == 0) { fence_cluster(); dsmem_stu(rxm_f, peer, mp); }
        while (lds_vol(rxm_f) < mp) {}
        fence_cluster();
        float peerU = rxm[mp & 3][0], peerL = rxm[mp & 3][1];
        if (few_u) {
            float ex = pmax_f_excl(cmx, fbuf);
            st.fbU = (sub == 1) ? fmaxf(ex, peerU) : ex;
        }
        if (few_l) {
            float ex = pmin_f_excl(cmn, fbuf);
            st.fbL = (sub == 1) ? fminf(ex, peerL) : ex;
        }
    }
    st.vl_u = (st.runl_u >= loG) ? hc[PH(st.runl_u - loG)] : pLPU;
    st.vl_l = (st.runl_l >= loG) ? hc[PH(st.runl_l - loG)] : pLPL;
    st.pFPU = pFPU; st.pFPL = pFPL;
    return st;
}

// walk B: fully branchless; values bitwise-identical to R9
__device__ void walkB(const float* __restrict__ hc, float* __restrict__ ho,
                      FS st, int sub,
                      float* rxh, unsigned* rxh_f, unsigned hp_out,
                      float& o_m, float& o_h2)
{
    const int t = threadIdx.x;
    const int lo = t * CHUNK;
    const int loG = sub * HALF, hiG = loG + HALF;
    const int gbase = loG + lo;
    const unsigned peer = (unsigned)(sub ^ 1);

    float h8[CHUNK];
    const float* cbase = hc + PH(lo);
    *(float4*)&h8[0] = ((const float4*)cbase)[0];
    *(float4*)&h8[4] = ((const float4*)cbase)[1];

    const bool few_u = (st.few & 1) != 0, few_l = (st.few & 2) != 0;
    int   runl_u = st.runl_u, runl_l = st.runl_l;
    float vl_u = st.vl_u, vl_l = st.vl_l;
    float fbU = st.fbU, fbL = st.fbL;
    float acc_m = 0.f, acc_h = 0.f;
    float firstO = 0.f, lastO = 0.f;
    float* obase = ho + PH(lo);

#pragma unroll
    for (int q = 0; q < 2; ++q) {
        float4 ov;
#pragma unroll
        for (int r = 0; r < 4; ++r) {
            const int j = 4 * q + r;
            const int gi = gbase + j;
            const float hv = h8[j];

            if ((st.mU >> j) & 1u) { runl_u = gi; vl_u = hv; }
            unsigned remU = st.mU >> j;
            int nu = remU ? gi + (__ffs(remU) - 1) : st.off_nu;
            float ldU = hc[PH(min(nu - loG, HALF - 1))];   // nu >= gi >= loG always
            float vr_u = (nu < hiG) ? ldU : st.pFPU;
            int den_u = nu - runl_u;
            float eu = (den_u > 0)
                ? vl_u + ((float)(gi - runl_u) / (float)den_u) * (vr_u - vl_u)
                : vl_u;                       // den==0 -> at peak (discarded div ok)
            if (runl_u < 0) eu = vr_u;        // left of first peak
            if (nu >= L)    eu = vl_u;        // right of last peak
            if (few_u) { fbU = fmaxf(fbU, hv); eu = fbU; }

            if ((st.mL >> j) & 1u) { runl_l = gi; vl_l = hv; }
            unsigned remL = st.mL >> j;
            int nl = remL ? gi + (__ffs(remL) - 1) : st.off_nl;
            float ldL = hc[PH(min(nl - loG, HALF - 1))];
            float vr_l = (nl < hiG) ? ldL : st.pFPL;
            int den_l = nl - runl_l;
            float el = (den_l > 0)
                ? vl_l + ((float)(gi - runl_l) / (float)den_l) * (vr_l - vl_l)
                : vl_l;
            if (runl_l < 0) el = vr_l;
            if (nl >= L)    el = vl_l;
            if (few_l) { fbL = fminf(fbL, hv); el = fbL; }

            float mean = 0.5f * (eu + el);
            float o = hv - mean;
            if (j == 0) firstO = o;
            lastO = o;
            acc_m += mean * mean;
            acc_h += hv * hv;
            switch (r) {
                case 0: ov.x = o; break;
                case 1: ov.y = o; break;
                case 2: ov.z = o; break;
                default: ov.w = o; break;
            }
        }
        ((float4*)obase)[q] = ov;
    }
    o_m = acc_m; o_h2 = acc_h;

    if (sub == 0 && t == NT - 1) halo_push(rxh, rxh_f, peer, hp_out, lastO);
    if (sub == 1 && t == 0)      halo_push(rxh, rxh_f, peer, hp_out, firstO);
}

__global__ void __launch_bounds__(NT, 1) __cluster_dims__(2, 1, 1)
emd_kernel(const float* __restrict__ x, float* __restrict__ out)
{
    extern __shared__ unsigned char dynsm[];
    float* bufA = (float*)dynsm;
    float* bufB = bufA + LPH;

    __shared__ unsigned s_u[3 * NW + 3];
    __shared__ float    s_f[NW + 1];
    __shared__ double   s_d[4 * NW];
    __shared__ double   s_d2[16];
    __shared__ int      s_flag;
    __shared__ float    s_rxh[4];
    __shared__ float    s_rxm[4][9];
    __shared__ unsigned s_rxh_f, s_rxm_f;

    const int t   = threadIdx.x;
    const int lo  = t * CHUNK;
    const int cta = blockIdx.x;
    const int row = cta >> 1;
    unsigned rk;
    asm("mov.u32 %0, %%cluster_ctarank;" : "=r"(rk));
    const int sub = (int)rk;
    const unsigned peer = (unsigned)(sub ^ 1);

    if (t == 0) { s_rxh_f = 0u; s_rxm_f = 0u; }
    __syncthreads();
    CLUSTER_SYNC();   // flags initialized in both CTAs before any remote push

    const float* xr   = x + (size_t)row * L + sub * HALF;
    float*       resr = g_res + (size_t)row * L + sub * HALF;
#pragma unroll
    for (int q = 0; q < 2; ++q)
        *(float4*)(resr + lo + 4 * q) = *(const float4*)(xr + lo + 4 * q);

    unsigned tag = 1, hp = 0, mp = 0;
    bool outer_done = false;

    for (int im = 0; im < NIMF; ++im) {
        float* outim = out + ((size_t)im * BROWS + row) * L + sub * HALF;
        if (outer_done) {
            float4 z = make_float4(0.f, 0.f, 0.f, 0.f);
#pragma unroll
            for (int q = 0; q < 2; ++q) *(float4*)(outim + lo + 4 * q) = z;
            continue;  // globally uniform
        }

        float* hc = bufA;
        float* ho = bufB;
#pragma unroll
        for (int q = 0; q < 2; ++q)
            ((float4*)(hc + PH(lo)))[q] = *(const float4*)(resr + lo + 4 * q);
        __syncthreads();

        hp++;
        if (sub == 0 && t == NT - 1) halo_push(s_rxh, &s_rxh_f, peer, hp, hc[PH(HALF - 1)]);
        if (sub == 1 && t == 0)      halo_push(s_rxh, &s_rxh_f, peer, hp, hc[PH(0)]);
        FS st = front(hc, sub, s_u, s_f, s_rxh, &s_rxh_f, s_rxm, &s_rxm_f, hp, mp);

        for (int it = 0; it < MAXIT; ++it) {
            float fm, fh2;
            hp++;
            walkB(hc, ho, st, sub, s_rxh, &s_rxh_f, hp, fm, fh2);
            double sm = (double)fm, sh2 = (double)fh2;
            block_sum2_to0(sm, sh2, s_d);
            if (t == 0) {
                double* p = &g_part[tag & 1][cta][0];
                p[0] = sm; p[1] = sh2;
                __threadfence();
                ((volatile unsigned*)g_seq)[cta] = tag;
            }
            // speculative front for next iteration, hidden under the grid sync
            FS st2;
            const bool spec = (it + 1 < MAXIT);
            if (spec)
                st2 = front(ho, sub, s_u, s_f, s_rxh, &s_rxh_f, s_rxm, &s_rxm_f, hp, mp);
            if (t < NCTA) {
                volatile unsigned* sq = &g_seq[t];
                while (*sq < tag) {}
            }
            __threadfence();
            if (t < NCTA) {
                volatile double* p = &g_part[tag & 1][t][0];
                double a = p[0], b = p[1];
#pragma unroll
                for (int d = 16; d; d >>= 1) {
                    a += __shfl_down_sync(0xffffffffu, a, d);
                    b += __shfl_down_sync(0xffffffffu, b, d);
                }
                if ((t & 31) == 0) { s_d2[t >> 5] = a; s_d2[4 + (t >> 5)] = b; }
            }
            __syncthreads();
            if (t == 0) {
                double A  = (s_d2[0] + s_d2[1]) + (s_d2[2] + s_d2[3]);
                double Bs = (s_d2[4] + s_d2[5]) + (s_d2[6] + s_d2[7]);
                s_flag = (A / (Bs + 1e-8) < 0.05) ? 1 : 0;
            }
            tag++;
            __syncthreads();
            if (s_flag) break;
            float* tmp = hc; hc = ho; ho = tmp;
            st = st2;
        }

        // emit IMF, update residual
        float ar = 0.f, ar2 = 0.f;
#pragma unroll
        for (int q = 0; q < 2; ++q) {
            float4 hv = ((const float4*)(hc + PH(lo)))[q];
            float4 rr = *(const float4*)(resr + lo + 4 * q);
            float4 nr;
            nr.x = rr.x - hv.x; nr.y = rr.y - hv.y;
            nr.z = rr.z - hv.z; nr.w = rr.w - hv.w;
            *(float4*)(outim + lo + 4 * q) = hv;
            *(float4*)(resr + lo + 4 * q)  = nr;
            ((float4*)(ho + PH(lo)))[q]    = nr;
            ar  += nr.x + nr.y + nr.z + nr.w;
            ar2 += nr.x * nr.x + nr.y * nr.y + nr.z * nr.z + nr.w * nr.w;
        }
        __syncthreads();
        hp++;
        if (sub == 0 && t == NT - 1) halo_push(s_rxh, &s_rxh_f, peer, hp, ho[PH(HALF - 1)]);
        if (sub == 1 && t == 0)      halo_push(s_rxh, &s_rxh_f, peer, hp, ho[PH(0)]);

        float ad = 0.f, ad2 = 0.f;
        {
            float c8[CHUNK];
#pragma unroll
            for (int q = 0; q < 2; ++q)
                *(float4*)&c8[4 * q] = ((const float4*)(ho + PH(lo)))[q];
            float nb;
            if (t < NT - 1)    nb = ho[PH(lo + CHUNK)];
            else if (sub == 0) nb = halo_wait(s_rxh, &s_rxh_f, hp);
            else               nb = 0.f;
#pragma unroll
            for (int j = 0; j < CHUNK; ++j) {
                float nx = (j < CHUNK - 1) ? c8[j + 1] : nb;
                if (sub * HALF + lo + j < L - 1) {
                    float d = nx - c8[j];
                    ad  += d;
                    ad2 += d * d;
                }
            }
        }
        double Sd = (double)ad, Sd2 = (double)ad2;
        double Sr = (double)ar, Sr2 = (double)ar2;
        block_sum4_to0(Sd, Sd2, Sr, Sr2, s_d);
        if (t == 0) {
            double* p = &g_part[tag & 1][cta][0];
            p[0] = Sd; p[1] = Sd2; p[2] = Sr; p[3] = Sr2;
            __threadfence();
            ((volatile unsigned*)g_seq)[cta] = tag;
        }
        if (t < NCTA) {
            volatile unsigned* sq = &g_seq[t];
            while (*sq < tag) {}
        }
        __threadfence();
        if (t < NCTA) {
            volatile double* p = &g_part[tag & 1][t][0];
            double a = p[0], b = p[1], c = p[2], e = p[3];
#pragma unroll
            for (int d = 16; d; d >>= 1) {
                a += __shfl_down_sync(0xffffffffu, a, d);
                b += __shfl_down_sync(0xffffffffu, b, d);
                c += __shfl_down_sync(0xffffffffu, c, d);
                e += __shfl_down_sync(0xffffffffu, e, d);
            }
            if ((t & 31) == 0) {
                int w = t >> 5;
                s_d2[4 * w + 0] = a; s_d2[4 * w + 1] = b;
                s_d2[4 * w + 2] = c; s_d2[4 * w + 3] = e;
            }
        }
        __syncthreads();
        if (t == 0) {
            double a = (s_d2[0] + s_d2[4]) + (s_d2[8] + s_d2[12]);
            double b = (s_d2[1] + s_d2[5]) + (s_d2[9] + s_d2[13]);
            double c = (s_d2[2] + s_d2[6]) + (s_d2[10] + s_d2[14]);
            double e = (s_d2[3] + s_d2[7]) + (s_d2[11] + s_d2[15]);
            double ndv = (double)BROWS * (double)(L - 1);
            double nrv = (double)BROWS * (double)L;
            double vard = (b - a * a / ndv) / (ndv - 1.0);
            double varr = (e - c * c / nrv) / (nrv - 1.0);
            s_flag = (vard < 0.05 * varr) ? 1 : 0;
        }
        tag++;
        __syncthreads();
        if (s_flag) outer_done = true;
    }

    float* outres = out + ((size_t)NIMF * BROWS + row) * L + sub * HALF;
#pragma unroll
    for (int q = 0; q < 2; ++q)
        *(float4*)(outres + lo + 4 * q) = *(const float4*)(resr + lo + 4 * q);

    // end-of-launch rendezvous + reset for graph replays
    __syncthreads();
    if (t == 0) {
        __threadfence();
        atomicAdd(&g_count, 1u);
    }
    if (cta == 0) {
        if (t == 0) {
            volatile unsigned* vc = &g_count;
            while (*vc < (unsigned)NCTA) {}
            __threadfence();
        }
        __syncthreads();
        if (t < NCTA) ((volatile unsigned*)g_seq)[t] = 0u;
        if (t == 0) g_count = 0u;
    }
    CLUSTER_SYNC();   // no CTA exits while peer may still remote-write its smem
}

extern "C" void kernel_launch(void* const* d_in, const int* in_sizes, int n_in,
                              void* d_out, int out_size) {
    (void)in_sizes; (void)n_in; (void)out_size;
    const size_t shmem = (size_t)(2 * LPH) * sizeof(float);
    cudaFuncSetAttribute(emd_kernel, cudaFuncAttributeMaxDynamicSharedMemorySize, (int)shmem);
    emd_kernel<<<NCTA, NT, shmem>>>((const float*)d_in[0], (float*)d_out);
}